// round 4
// baseline (speedup 1.0000x reference)
#include <cuda_runtime.h>
#include <math.h>

#define Bn 2
#define Tn 2048
#define Cn 2048
#define Hn 16
#define Dn 128

// Scratch (no allocations allowed): qkv = 96MB, att = 32MB
__device__ float g_qkv[(size_t)Bn * Tn * 3 * Cn];
__device__ float g_att[(size_t)Bn * Tn * Cn];

// ---------------------------------------------------------------------------
// Classic SIMT SGEMM: 128x128 block tile, BK=8, 256 threads, 8x8 per thread.
// C[M,N] = A[M,K] @ B[K,N], all row-major, dims divisible by 128/8.
// ---------------------------------------------------------------------------
__global__ __launch_bounds__(256) void sgemm128(const float* __restrict__ A,
                                                const float* __restrict__ B,
                                                float* __restrict__ C,
                                                int M, int N, int K) {
    __shared__ float As[8][128];   // transposed A tile: As[k][m]
    __shared__ float Bs[8][128];   // Bs[k][n]

    const int tid  = threadIdx.x;
    const int brow = blockIdx.y * 128;
    const int bcol = blockIdx.x * 128;

    const int arow = tid >> 1;            // 0..127
    const int acol = (tid & 1) * 4;       // 0 or 4
    const int brw  = tid >> 5;            // 0..7
    const int bcl  = (tid & 31) * 4;      // 0..124

    const int ra = (tid >> 4) * 4;        // row base (split halves +64)
    const int cb = (tid & 15) * 4;        // col base (split halves +64)

    const float* Ap = A + (size_t)(brow + arow) * K + acol;
    const float* Bp = B + (size_t)brw * N + bcol + bcl;

    float acc[8][8];
#pragma unroll
    for (int i = 0; i < 8; i++)
#pragma unroll
        for (int j = 0; j < 8; j++) acc[i][j] = 0.f;

    for (int k0 = 0; k0 < K; k0 += 8) {
        float4 av = *(const float4*)Ap;
        float4 bv = *(const float4*)Bp;
        Ap += 8;
        Bp += (size_t)8 * N;

        As[acol + 0][arow] = av.x;
        As[acol + 1][arow] = av.y;
        As[acol + 2][arow] = av.z;
        As[acol + 3][arow] = av.w;
        *(float4*)&Bs[brw][bcl] = bv;
        __syncthreads();

#pragma unroll
        for (int k = 0; k < 8; k++) {
            float a[8], b[8];
            *(float4*)(a)     = *(const float4*)&As[k][ra];
            *(float4*)(a + 4) = *(const float4*)&As[k][ra + 64];
            *(float4*)(b)     = *(const float4*)&Bs[k][cb];
            *(float4*)(b + 4) = *(const float4*)&Bs[k][cb + 64];
#pragma unroll
            for (int i = 0; i < 8; i++)
#pragma unroll
                for (int j = 0; j < 8; j++)
                    acc[i][j] += a[i] * b[j];
        }
        __syncthreads();
    }

#pragma unroll
    for (int i = 0; i < 8; i++) {
        int r = brow + ((i < 4) ? (ra + i) : (ra + 64 + (i - 4)));
        float4 v0 = make_float4(acc[i][0], acc[i][1], acc[i][2], acc[i][3]);
        float4 v1 = make_float4(acc[i][4], acc[i][5], acc[i][6], acc[i][7]);
        *(float4*)&C[(size_t)r * N + bcol + cb]      = v0;
        *(float4*)&C[(size_t)r * N + bcol + cb + 64] = v1;
    }
}

// ---------------------------------------------------------------------------
// RoPE applied in-place to q and k slices of the qkv buffer.
// Also folds the 1/sqrt(D) attention scale into q.
// qkv row layout: [3][H][D] = 6144 floats per (b,t).
// ---------------------------------------------------------------------------
__global__ void rope_kernel(float* __restrict__ qkv,
                            const float* __restrict__ cosb,
                            const float* __restrict__ sinb) {
    int idx = blockIdx.x * blockDim.x + threadIdx.x;
    if (idx >= Bn * Tn * Hn * 64) return;
    int d2  = idx & 63;
    int h   = (idx >> 6) & (Hn - 1);
    int row = idx >> 10;            // 64 * 16 = 1024
    int t   = row & (Tn - 1);

    float c = cosb[t * 64 + d2];
    float s = sinb[t * 64 + d2];
    const float scale = 0.08838834764831845f;  // 1/sqrt(128)

    size_t base = (size_t)row * 6144 + h * 128;
    float q1 = qkv[base + d2], q2 = qkv[base + 64 + d2];
    qkv[base + d2]      = (q1 * c - q2 * s) * scale;
    qkv[base + 64 + d2] = (q2 * c + q1 * s) * scale;

    size_t kb = base + 2048;
    float k1 = qkv[kb + d2], k2 = qkv[kb + 64 + d2];
    qkv[kb + d2]      = k1 * c - k2 * s;
    qkv[kb + 64 + d2] = k2 * c + k1 * s;
}

// ---------------------------------------------------------------------------
// Flash-attention (causal, online softmax).
// Block: 256 threads; tile Tq=64 x Tk=64, D=128.
// Smem: Q[64][128], K^T[128][65] (pad for conflict-free), V[64][128], S[64][64].
// Thread (tx,ty): tx=tid&15, ty=tid>>4. S-phase: 4x4 per thread.
// PV-phase: rows ty*4+i, cols tx+16*jj.
// ---------------------------------------------------------------------------
#define BQ 64
#define BKT 64

extern __shared__ float sm_f[];

__global__ __launch_bounds__(256) void flash_kernel(const float* __restrict__ qkv,
                                                    float* __restrict__ att) {
    float* Qs = sm_f;                       // 64*128
    float* Kt = Qs + 64 * 128;              // 128*65
    float* Vs = Kt + 128 * 65;              // 64*128
    float* Ss = Vs + 64 * 128;              // 64*64

    const int tid = threadIdx.x;
    const int tx  = tid & 15;
    const int ty  = tid >> 4;
    const int qb  = blockIdx.x * BQ;
    const int b   = blockIdx.y >> 4;
    const int h   = blockIdx.y & (Hn - 1);

    // Load Q tile (stays resident across k-tiles)
    const float* qbase = qkv + ((size_t)(b * Tn + qb)) * 6144 + h * 128;
    for (int i = tid; i < BQ * 32; i += 256) {
        int r = i >> 5, c = (i & 31) << 2;
        *(float4*)&Qs[r * 128 + c] = *(const float4*)(qbase + (size_t)r * 6144 + c);
    }

    float o[4][8];
    float m[4], l[4];
#pragma unroll
    for (int i = 0; i < 4; i++) {
        m[i] = -1e30f; l[i] = 0.f;
#pragma unroll
        for (int j = 0; j < 8; j++) o[i][j] = 0.f;
    }

    for (int kb = 0; kb <= qb; kb += BKT) {
        __syncthreads();  // protects Qs on first iter, Kt/Vs/Ss reuse after

        const float* kbase = qkv + ((size_t)(b * Tn + kb)) * 6144 + 2048 + h * 128;
        const float* vbase = kbase + 2048;

        // K transposed into smem (coalesced gmem read, conflict-free STS)
        for (int i = tid; i < BKT * 128; i += 256) {
            int j = i >> 7, d = i & 127;
            Kt[d * 65 + j] = kbase[(size_t)j * 6144 + d];
        }
        // V tile
        for (int i = tid; i < BKT * 32; i += 256) {
            int j = i >> 5, c = (i & 31) << 2;
            *(float4*)&Vs[j * 128 + c] = *(const float4*)(vbase + (size_t)j * 6144 + c);
        }
        __syncthreads();

        // ---- S = Q K^T (4x4 per thread) ----
        float s[4][4];
#pragma unroll
        for (int i = 0; i < 4; i++)
#pragma unroll
            for (int j = 0; j < 4; j++) s[i][j] = 0.f;

#pragma unroll 2
        for (int d0 = 0; d0 < 128; d0 += 4) {
            float4 q0 = *(const float4*)&Qs[(ty * 4 + 0) * 128 + d0];
            float4 q1 = *(const float4*)&Qs[(ty * 4 + 1) * 128 + d0];
            float4 q2 = *(const float4*)&Qs[(ty * 4 + 2) * 128 + d0];
            float4 q3 = *(const float4*)&Qs[(ty * 4 + 3) * 128 + d0];
            const float* qa0 = (const float*)&q0;
            const float* qa1 = (const float*)&q1;
            const float* qa2 = (const float*)&q2;
            const float* qa3 = (const float*)&q3;
#pragma unroll
            for (int dd = 0; dd < 4; dd++) {
                float b0 = Kt[(d0 + dd) * 65 + tx * 4 + 0];
                float b1 = Kt[(d0 + dd) * 65 + tx * 4 + 1];
                float b2 = Kt[(d0 + dd) * 65 + tx * 4 + 2];
                float b3 = Kt[(d0 + dd) * 65 + tx * 4 + 3];
                float a0 = qa0[dd], a1 = qa1[dd], a2 = qa2[dd], a3 = qa3[dd];
                s[0][0] += a0 * b0; s[0][1] += a0 * b1; s[0][2] += a0 * b2; s[0][3] += a0 * b3;
                s[1][0] += a1 * b0; s[1][1] += a1 * b1; s[1][2] += a1 * b2; s[1][3] += a1 * b3;
                s[2][0] += a2 * b0; s[2][1] += a2 * b1; s[2][2] += a2 * b2; s[2][3] += a2 * b3;
                s[3][0] += a3 * b0; s[3][1] += a3 * b1; s[3][2] += a3 * b2; s[3][3] += a3 * b3;
            }
        }

        // causal mask (only the diagonal tile needs it: kb == qb)
        if (kb == qb) {
#pragma unroll
            for (int i = 0; i < 4; i++)
#pragma unroll
                for (int j = 0; j < 4; j++)
                    if (tx * 4 + j > ty * 4 + i) s[i][j] = -1e30f;
        }

        // ---- online softmax update (row groups = 16 lanes sharing ty) ----
#pragma unroll
        for (int i = 0; i < 4; i++) {
            float mx = fmaxf(fmaxf(s[i][0], s[i][1]), fmaxf(s[i][2], s[i][3]));
#pragma unroll
            for (int off = 8; off > 0; off >>= 1)
                mx = fmaxf(mx, __shfl_xor_sync(0xffffffffu, mx, off));
            float mnew = fmaxf(m[i], mx);
            float cf = __expf(m[i] - mnew);
            float rs = 0.f;
#pragma unroll
            for (int j = 0; j < 4; j++) {
                s[i][j] = __expf(s[i][j] - mnew);
                rs += s[i][j];
            }
#pragma unroll
            for (int off = 8; off > 0; off >>= 1)
                rs += __shfl_xor_sync(0xffffffffu, rs, off);
            l[i] = l[i] * cf + rs;
            m[i] = mnew;
#pragma unroll
            for (int jj = 0; jj < 8; jj++) o[i][jj] *= cf;
#pragma unroll
            for (int j = 0; j < 4; j++)
                Ss[(ty * 4 + i) * 64 + tx * 4 + j] = s[i][j];
        }
        __syncthreads();

        // ---- O += P V ----
        for (int j = 0; j < BKT; j++) {
            float p0 = Ss[(ty * 4 + 0) * 64 + j];
            float p1 = Ss[(ty * 4 + 1) * 64 + j];
            float p2 = Ss[(ty * 4 + 2) * 64 + j];
            float p3 = Ss[(ty * 4 + 3) * 64 + j];
#pragma unroll
            for (int jj = 0; jj < 8; jj++) {
                float v = Vs[j * 128 + tx + 16 * jj];
                o[0][jj] += p0 * v;
                o[1][jj] += p1 * v;
                o[2][jj] += p2 * v;
                o[3][jj] += p3 * v;
            }
        }
    }

    // epilogue: normalize, write to att[(b,t),(h,d)] layout (= transpose-merge)
    float* obase = att + ((size_t)(b * Tn + qb)) * 2048 + h * 128;
#pragma unroll
    for (int i = 0; i < 4; i++) {
        float inv = 1.f / l[i];
#pragma unroll
        for (int jj = 0; jj < 8; jj++)
            obase[(size_t)(ty * 4 + i) * 2048 + tx + 16 * jj] = o[i][jj] * inv;
    }
}

// ---------------------------------------------------------------------------
// Launch
// ---------------------------------------------------------------------------
extern "C" void kernel_launch(void* const* d_in, const int* in_sizes, int n_in,
                              void* d_out, int out_size) {
    const float *x = nullptr, *wqkv = nullptr, *wout = nullptr;
    const float *cosb = nullptr, *sinb = nullptr;
    for (int i = 0; i < n_in; i++) {
        int s = in_sizes[i];
        const float* p = (const float*)d_in[i];
        if (s == Bn * Tn * Cn)          x = p;
        else if (s == Cn * 3 * Cn)      wqkv = p;
        else if (s == Cn * Cn)          wout = p;
        else if (s == Tn * (Dn / 2)) {  // cos then sin, in metadata order
            if (!cosb) cosb = p; else sinb = p;
        }
    }

    float* qkv; float* att;
    cudaGetSymbolAddress((void**)&qkv, g_qkv);
    cudaGetSymbolAddress((void**)&att, g_att);

    // 1) QKV projection: (4096 x 2048) @ (2048 x 6144)
    dim3 blk(256);
    dim3 g1((3 * Cn) / 128, (Bn * Tn) / 128);
    sgemm128<<<g1, blk>>>(x, wqkv, qkv, Bn * Tn, 3 * Cn, Cn);

    // 2) RoPE (in-place, folds 1/sqrt(D) into q)
    int total = Bn * Tn * Hn * 64;
    rope_kernel<<<(total + 255) / 256, 256>>>(qkv, cosb, sinb);

    // 3) Causal flash attention
    size_t smem = (size_t)(64 * 128 + 128 * 65 + 64 * 128 + 64 * 64) * sizeof(float);
    cudaFuncSetAttribute(flash_kernel, cudaFuncAttributeMaxDynamicSharedMemorySize,
                         (int)smem);
    flash_kernel<<<dim3(Tn / BQ, Bn * Hn), blk, smem>>>(qkv, att);

    // 4) Output projection: (4096 x 2048) @ (2048 x 2048)
    dim3 g2(Cn / 128, (Bn * Tn) / 128);
    sgemm128<<<g2, blk>>>(att, wout, (float*)d_out, Bn * Tn, Cn, Cn);
}

// round 7
// speedup vs baseline: 1.3161x; 1.3161x over previous
#include <cuda_runtime.h>
#include <math.h>
#include <stdint.h>
#include <mma.h>

using namespace nvcuda;

#define Bn 2
#define Tn 2048
#define Cn 2048
#define Hn 16
#define Dn 128

// Scratch (no allocations allowed)
__device__ float g_qkv[(size_t)Bn * Tn * 3 * Cn];     // 96 MB
__device__ float g_att[(size_t)Bn * Tn * Cn];         // 32 MB
__device__ float g_wqkvT[(size_t)3 * Cn * Cn];        // 48 MB
__device__ float g_woutT[(size_t)Cn * Cn];            // 16 MB

__device__ __forceinline__ uint4 cvt_tf32x4(float4 v) {
    uint4 u;
    asm("cvt.rna.tf32.f32 %0, %1;" : "=r"(u.x) : "f"(v.x));
    asm("cvt.rna.tf32.f32 %0, %1;" : "=r"(u.y) : "f"(v.y));
    asm("cvt.rna.tf32.f32 %0, %1;" : "=r"(u.z) : "f"(v.z));
    asm("cvt.rna.tf32.f32 %0, %1;" : "=r"(u.w) : "f"(v.w));
    return u;
}

// ---------------------------------------------------------------------------
// Weight transpose: out[c][r] = in[r][c]  (R, C multiples of 32)
// ---------------------------------------------------------------------------
__global__ void transpose_k(const float* __restrict__ in, float* __restrict__ out,
                            int R, int C) {
    __shared__ float t[32][33];
    int bx = blockIdx.x * 32, by = blockIdx.y * 32;
    int tx = threadIdx.x, ty = threadIdx.y;  // 32 x 8
#pragma unroll
    for (int i = 0; i < 32; i += 8)
        t[ty + i][tx] = in[(size_t)(by + ty + i) * C + bx + tx];
    __syncthreads();
#pragma unroll
    for (int i = 0; i < 32; i += 8)
        out[(size_t)(bx + ty + i) * R + by + tx] = t[tx][ty + i];
}

// ---------------------------------------------------------------------------
// wmma tf32 GEMM: C[M,N] = A[M,K] @ BT[N,K]^T   (both operands K-major)
// CTA 128x128, BK=32, 8 warps (32m x 64n warp tile, m16n16k8 fragments).
// Inputs rounded to tf32 (cvt.rna) during the smem fill.
// ---------------------------------------------------------------------------
#define BKg 32
#define LDT 36   // 32 + 4 pad: 16B-aligned rows, de-correlated banks

__global__ __launch_bounds__(256, 2) void gemm_tf32w(const float* __restrict__ A,
                                                     const float* __restrict__ BT,
                                                     float* __restrict__ C,
                                                     int M, int N, int K) {
    __shared__ float As[128 * LDT];
    __shared__ float Bs[128 * LDT];

    const int tid  = threadIdx.x;
    const int warp = tid >> 5;
    const int wm   = warp >> 1;          // 0..3 -> m offset wm*32
    const int wn   = warp & 1;           // 0..1 -> n offset wn*64
    const int m0   = blockIdx.y * 128;
    const int n0   = blockIdx.x * 128;

    wmma::fragment<wmma::accumulator, 16, 16, 8, float> c[2][4];
#pragma unroll
    for (int i = 0; i < 2; i++)
#pragma unroll
        for (int j = 0; j < 4; j++) wmma::fill_fragment(c[i][j], 0.0f);

    for (int k0 = 0; k0 < K; k0 += BKg) {
        __syncthreads();
        // Fill: 128 rows x 32 tf32 for A and B tiles (coalesced 128B segments)
#pragma unroll
        for (int t = 0; t < 4; t++) {
            int f  = tid + 256 * t;          // 0..1023
            int r  = f >> 3;
            int c4 = (f & 7) << 2;
            float4 va = *(const float4*)&A [(size_t)(m0 + r) * K + k0 + c4];
            float4 vb = *(const float4*)&BT[(size_t)(n0 + r) * K + k0 + c4];
            *(uint4*)&As[r * LDT + c4] = cvt_tf32x4(va);
            *(uint4*)&Bs[r * LDT + c4] = cvt_tf32x4(vb);
        }
        __syncthreads();

#pragma unroll
        for (int kk = 0; kk < BKg; kk += 8) {
            wmma::fragment<wmma::matrix_a, 16, 16, 8, wmma::precision::tf32,
                           wmma::row_major> a[2];
            wmma::fragment<wmma::matrix_b, 16, 16, 8, wmma::precision::tf32,
                           wmma::col_major> b[4];
#pragma unroll
            for (int i = 0; i < 2; i++)
                wmma::load_matrix_sync(a[i], &As[(wm * 32 + i * 16) * LDT + kk], LDT);
#pragma unroll
            for (int j = 0; j < 4; j++)
                wmma::load_matrix_sync(b[j], &Bs[(wn * 64 + j * 16) * LDT + kk], LDT);
#pragma unroll
            for (int i = 0; i < 2; i++)
#pragma unroll
                for (int j = 0; j < 4; j++)
                    wmma::mma_sync(c[i][j], a[i], b[j], c[i][j]);
        }
    }

#pragma unroll
    for (int i = 0; i < 2; i++)
#pragma unroll
        for (int j = 0; j < 4; j++)
            wmma::store_matrix_sync(
                &C[(size_t)(m0 + wm * 32 + i * 16) * N + n0 + wn * 64 + j * 16],
                c[i][j], N, wmma::mem_row_major);
}

// ---------------------------------------------------------------------------
// RoPE (in-place, folds 1/sqrt(D) into q)
// ---------------------------------------------------------------------------
__global__ void rope_kernel(float* __restrict__ qkv,
                            const float* __restrict__ cosb,
                            const float* __restrict__ sinb) {
    int idx = blockIdx.x * blockDim.x + threadIdx.x;
    if (idx >= Bn * Tn * Hn * 64) return;
    int d2  = idx & 63;
    int h   = (idx >> 6) & (Hn - 1);
    int row = idx >> 10;
    int t   = row & (Tn - 1);

    float c = cosb[t * 64 + d2];
    float s = sinb[t * 64 + d2];
    const float scale = 0.08838834764831845f;

    size_t base = (size_t)row * 6144 + h * 128;
    float q1 = qkv[base + d2], q2 = qkv[base + 64 + d2];
    qkv[base + d2]      = (q1 * c - q2 * s) * scale;
    qkv[base + 64 + d2] = (q2 * c + q1 * s) * scale;

    size_t kb = base + 2048;
    float k1 = qkv[kb + d2], k2 = qkv[kb + 64 + d2];
    qkv[kb + d2]      = k1 * c - k2 * s;
    qkv[kb + 64 + d2] = k2 * c + k1 * s;
}

// ---------------------------------------------------------------------------
// Flash-attention (causal, online softmax) — validated round-4 version
// ---------------------------------------------------------------------------
#define BQ 64
#define BKT 64

extern __shared__ float sm_f[];

__global__ __launch_bounds__(256) void flash_kernel(const float* __restrict__ qkv,
                                                    float* __restrict__ att) {
    float* Qs = sm_f;
    float* Kt = Qs + 64 * 128;
    float* Vs = Kt + 128 * 65;
    float* Ss = Vs + 64 * 128;

    const int tid = threadIdx.x;
    const int tx  = tid & 15;
    const int ty  = tid >> 4;
    const int qb  = blockIdx.x * BQ;
    const int b   = blockIdx.y >> 4;
    const int h   = blockIdx.y & (Hn - 1);

    const float* qbase = qkv + ((size_t)(b * Tn + qb)) * 6144 + h * 128;
    for (int i = tid; i < BQ * 32; i += 256) {
        int r = i >> 5, c = (i & 31) << 2;
        *(float4*)&Qs[r * 128 + c] = *(const float4*)(qbase + (size_t)r * 6144 + c);
    }

    float o[4][8];
    float m[4], l[4];
#pragma unroll
    for (int i = 0; i < 4; i++) {
        m[i] = -1e30f; l[i] = 0.f;
#pragma unroll
        for (int j = 0; j < 8; j++) o[i][j] = 0.f;
    }

    for (int kb = 0; kb <= qb; kb += BKT) {
        __syncthreads();

        const float* kbase = qkv + ((size_t)(b * Tn + kb)) * 6144 + 2048 + h * 128;
        const float* vbase = kbase + 2048;

        for (int i = tid; i < BKT * 128; i += 256) {
            int j = i >> 7, d = i & 127;
            Kt[d * 65 + j] = kbase[(size_t)j * 6144 + d];
        }
        for (int i = tid; i < BKT * 32; i += 256) {
            int j = i >> 5, c = (i & 31) << 2;
            *(float4*)&Vs[j * 128 + c] = *(const float4*)(vbase + (size_t)j * 6144 + c);
        }
        __syncthreads();

        float s[4][4];
#pragma unroll
        for (int i = 0; i < 4; i++)
#pragma unroll
            for (int j = 0; j < 4; j++) s[i][j] = 0.f;

#pragma unroll 2
        for (int d0 = 0; d0 < 128; d0 += 4) {
            float4 q0 = *(const float4*)&Qs[(ty * 4 + 0) * 128 + d0];
            float4 q1 = *(const float4*)&Qs[(ty * 4 + 1) * 128 + d0];
            float4 q2 = *(const float4*)&Qs[(ty * 4 + 2) * 128 + d0];
            float4 q3 = *(const float4*)&Qs[(ty * 4 + 3) * 128 + d0];
            const float* qa0 = (const float*)&q0;
            const float* qa1 = (const float*)&q1;
            const float* qa2 = (const float*)&q2;
            const float* qa3 = (const float*)&q3;
#pragma unroll
            for (int dd = 0; dd < 4; dd++) {
                float b0 = Kt[(d0 + dd) * 65 + tx * 4 + 0];
                float b1 = Kt[(d0 + dd) * 65 + tx * 4 + 1];
                float b2 = Kt[(d0 + dd) * 65 + tx * 4 + 2];
                float b3 = Kt[(d0 + dd) * 65 + tx * 4 + 3];
                float a0 = qa0[dd], a1 = qa1[dd], a2 = qa2[dd], a3 = qa3[dd];
                s[0][0] += a0 * b0; s[0][1] += a0 * b1; s[0][2] += a0 * b2; s[0][3] += a0 * b3;
                s[1][0] += a1 * b0; s[1][1] += a1 * b1; s[1][2] += a1 * b2; s[1][3] += a1 * b3;
                s[2][0] += a2 * b0; s[2][1] += a2 * b1; s[2][2] += a2 * b2; s[2][3] += a2 * b3;
                s[3][0] += a3 * b0; s[3][1] += a3 * b1; s[3][2] += a3 * b2; s[3][3] += a3 * b3;
            }
        }

        if (kb == qb) {
#pragma unroll
            for (int i = 0; i < 4; i++)
#pragma unroll
                for (int j = 0; j < 4; j++)
                    if (tx * 4 + j > ty * 4 + i) s[i][j] = -1e30f;
        }

#pragma unroll
        for (int i = 0; i < 4; i++) {
            float mx = fmaxf(fmaxf(s[i][0], s[i][1]), fmaxf(s[i][2], s[i][3]));
#pragma unroll
            for (int off = 8; off > 0; off >>= 1)
                mx = fmaxf(mx, __shfl_xor_sync(0xffffffffu, mx, off));
            float mnew = fmaxf(m[i], mx);
            float cf = __expf(m[i] - mnew);
            float rs = 0.f;
#pragma unroll
            for (int j = 0; j < 4; j++) {
                s[i][j] = __expf(s[i][j] - mnew);
                rs += s[i][j];
            }
#pragma unroll
            for (int off = 8; off > 0; off >>= 1)
                rs += __shfl_xor_sync(0xffffffffu, rs, off);
            l[i] = l[i] * cf + rs;
            m[i] = mnew;
#pragma unroll
            for (int jj = 0; jj < 8; jj++) o[i][jj] *= cf;
#pragma unroll
            for (int j = 0; j < 4; j++)
                Ss[(ty * 4 + i) * 64 + tx * 4 + j] = s[i][j];
        }
        __syncthreads();

        for (int j = 0; j < BKT; j++) {
            float p0 = Ss[(ty * 4 + 0) * 64 + j];
            float p1 = Ss[(ty * 4 + 1) * 64 + j];
            float p2 = Ss[(ty * 4 + 2) * 64 + j];
            float p3 = Ss[(ty * 4 + 3) * 64 + j];
#pragma unroll
            for (int jj = 0; jj < 8; jj++) {
                float v = Vs[j * 128 + tx + 16 * jj];
                o[0][jj] += p0 * v;
                o[1][jj] += p1 * v;
                o[2][jj] += p2 * v;
                o[3][jj] += p3 * v;
            }
        }
    }

    float* obase = att + ((size_t)(b * Tn + qb)) * 2048 + h * 128;
#pragma unroll
    for (int i = 0; i < 4; i++) {
        float inv = 1.f / l[i];
#pragma unroll
        for (int jj = 0; jj < 8; jj++)
            obase[(size_t)(ty * 4 + i) * 2048 + tx + 16 * jj] = o[i][jj] * inv;
    }
}

// ---------------------------------------------------------------------------
// Launch
// ---------------------------------------------------------------------------
extern "C" void kernel_launch(void* const* d_in, const int* in_sizes, int n_in,
                              void* d_out, int out_size) {
    const float *x = nullptr, *wqkv = nullptr, *wout = nullptr;
    const float *cosb = nullptr, *sinb = nullptr;
    for (int i = 0; i < n_in; i++) {
        int s = in_sizes[i];
        const float* p = (const float*)d_in[i];
        if (s == Bn * Tn * Cn)          x = p;
        else if (s == Cn * 3 * Cn)      wqkv = p;
        else if (s == Cn * Cn)          wout = p;
        else if (s == Tn * (Dn / 2)) {
            if (!cosb) cosb = p; else sinb = p;
        }
    }

    float *qkv, *att, *wqkvT, *woutT;
    cudaGetSymbolAddress((void**)&qkv, g_qkv);
    cudaGetSymbolAddress((void**)&att, g_att);
    cudaGetSymbolAddress((void**)&wqkvT, g_wqkvT);
    cudaGetSymbolAddress((void**)&woutT, g_woutT);

    // 0) Transpose weights so both GEMM operands are K-major
    transpose_k<<<dim3((3 * Cn) / 32, Cn / 32), dim3(32, 8)>>>(wqkv, wqkvT, Cn, 3 * Cn);
    transpose_k<<<dim3(Cn / 32, Cn / 32), dim3(32, 8)>>>(wout, woutT, Cn, Cn);

    // 1) QKV projection (wmma tf32): [4096,2048] @ [2048,6144]
    gemm_tf32w<<<dim3((3 * Cn) / 128, (Bn * Tn) / 128), 256>>>(
        x, wqkvT, qkv, Bn * Tn, 3 * Cn, Cn);

    // 2) RoPE
    int total = Bn * Tn * Hn * 64;
    rope_kernel<<<(total + 255) / 256, 256>>>(qkv, cosb, sinb);

    // 3) Causal flash attention
    size_t smem = (size_t)(64 * 128 + 128 * 65 + 64 * 128 + 64 * 64) * sizeof(float);
    cudaFuncSetAttribute(flash_kernel, cudaFuncAttributeMaxDynamicSharedMemorySize,
                         (int)smem);
    flash_kernel<<<dim3(Tn / BQ, Bn * Hn), 256, smem>>>(qkv, att);

    // 4) Output projection (wmma tf32): [4096,2048] @ [2048,2048]
    gemm_tf32w<<<dim3(Cn / 128, (Bn * Tn) / 128), 256>>>(
        att, woutT, (float*)d_out, Bn * Tn, Cn, Cn);
}